// round 5
// baseline (speedup 1.0000x reference)
#include <cuda_runtime.h>
#include <math.h>

#define NPTS 262144
#define NLVL 16
#define TSZ  (1u << 19)
#define TMASK (TSZ - 1u)
#define NTILES 2048
#define GRID 296

typedef unsigned long long u64t;

__device__ __forceinline__ u64t pk2(float a, float b) {
    u64t r; asm("mov.b64 %0,{%1,%2};" : "=l"(r) : "f"(a), "f"(b)); return r;
}
__device__ __forceinline__ void upk2(u64t v, float& a, float& b) {
    asm("mov.b64 {%0,%1},%2;" : "=f"(a), "=f"(b) : "l"(v));
}
__device__ __forceinline__ void fma2(u64t& d, u64t a, u64t b) {
    asm("fma.rn.f32x2 %0,%1,%2,%0;" : "+l"(d) : "l"(a), "l"(b));
}
#define BARC() asm volatile("bar.sync 1, 128;" ::: "memory")

// ---------------------------------------------------------------------------
constexpr int OFF_SW0 = 0;            // 32*64
constexpr int OFF_SW1 = 2048;         // 64*64
constexpr int OFF_SW2 = 6144;         // 64*16
constexpr int OFF_CW0 = 7168;         // 42*64
constexpr int OFF_CW1 = 9856;         // 64*64
constexpr int OFF_CW2 = 13952;        // 64*3
constexpr int W_TOTAL = 14144;
__constant__ float c_w[W_TOTAL];

__constant__ int c_res[NLVL] = {16, 20, 25, 32, 40, 50, 64, 80,
                                101, 128, 161, 203, 256, 322, 406, 512};

constexpr int BP = 128;
constexpr int S  = 132;
// smem: F0,F1 (32 rows each), B0,B1 (64 rows each)
constexpr int OFF_F0 = 0;
constexpr int OFF_F1 = 32 * S;
constexpr int OFF_B0 = 64 * S;
constexpr int OFF_B1 = 128 * S;
constexpr int SMEM_FLOATS = 192 * S;             // 25344
constexpr int SMEM_BYTES  = SMEM_FLOATS * 4;     // 101376

// ---------------------------------------------------------------------------
// Consumer GEMM: warp -> 16 neurons, lane -> 4 points. FFMA2 throughout.
// ---------------------------------------------------------------------------
template <int IN, bool RELU>
__device__ __forceinline__ void gemmW(const float* __restrict__ xb,
                                      float* __restrict__ yb,
                                      int woff, int warp, int lane)
{
    u64t acc[16][2];
    #pragma unroll
    for (int n = 0; n < 16; n++) { acc[n][0] = 0ull; acc[n][1] = 0ull; }

    const float* xr = xb + lane * 4;
    const int wb = woff + warp * 16;
    #pragma unroll 4
    for (int i = 0; i < IN; i++) {
        float4 xv = *(const float4*)(xr + i * S);
        u64t x01 = pk2(xv.x, xv.y);
        u64t x23 = pk2(xv.z, xv.w);
        #pragma unroll
        for (int g = 0; g < 4; g++) {
            float4 w = *(const float4*)(c_w + wb + i * 64 + g * 4);
            u64t wd;
            wd = pk2(w.x, w.x);
            fma2(acc[g*4+0][0], x01, wd); fma2(acc[g*4+0][1], x23, wd);
            wd = pk2(w.y, w.y);
            fma2(acc[g*4+1][0], x01, wd); fma2(acc[g*4+1][1], x23, wd);
            wd = pk2(w.z, w.z);
            fma2(acc[g*4+2][0], x01, wd); fma2(acc[g*4+2][1], x23, wd);
            wd = pk2(w.w, w.w);
            fma2(acc[g*4+3][0], x01, wd); fma2(acc[g*4+3][1], x23, wd);
        }
    }
    #pragma unroll
    for (int n = 0; n < 16; n++) {
        float a0, a1, a2, a3;
        upk2(acc[n][0], a0, a1);
        upk2(acc[n][1], a2, a3);
        if (RELU) {
            a0 = fmaxf(a0, 0.f); a1 = fmaxf(a1, 0.f);
            a2 = fmaxf(a2, 0.f); a3 = fmaxf(a3, 0.f);
        }
        *(float4*)(yb + (warp * 16 + n) * S + lane * 4) =
            make_float4(a0, a1, a2, a3);
    }
}

// sw2 (64 -> 16): warp -> 4 neurons
__device__ __forceinline__ void gemm16W(const float* __restrict__ xb,
                                        float* __restrict__ yb,
                                        int warp, int lane)
{
    u64t acc[4][2];
    #pragma unroll
    for (int n = 0; n < 4; n++) { acc[n][0] = 0ull; acc[n][1] = 0ull; }

    const float* xr = xb + lane * 4;
    #pragma unroll 8
    for (int i = 0; i < 64; i++) {
        float4 xv = *(const float4*)(xr + i * S);
        u64t x01 = pk2(xv.x, xv.y);
        u64t x23 = pk2(xv.z, xv.w);
        float4 w = *(const float4*)(c_w + OFF_SW2 + i * 16 + warp * 4);
        u64t wd;
        wd = pk2(w.x, w.x); fma2(acc[0][0], x01, wd); fma2(acc[0][1], x23, wd);
        wd = pk2(w.y, w.y); fma2(acc[1][0], x01, wd); fma2(acc[1][1], x23, wd);
        wd = pk2(w.z, w.z); fma2(acc[2][0], x01, wd); fma2(acc[2][1], x23, wd);
        wd = pk2(w.w, w.w); fma2(acc[3][0], x01, wd); fma2(acc[3][1], x23, wd);
    }
    #pragma unroll
    for (int n = 0; n < 4; n++) {
        float a0, a1, a2, a3;
        upk2(acc[n][0], a0, a1);
        upk2(acc[n][1], a2, a3);
        *(float4*)(yb + (warp * 4 + n) * S + lane * 4) =
            make_float4(a0, a1, a2, a3);
    }
}

// ---------------------------------------------------------------------------
// Producer: hash one point, all 16 levels, into feature buffer F.
// ---------------------------------------------------------------------------
__device__ __forceinline__ void hash_point(const float* __restrict__ xyzt,
                                           const float* __restrict__ table,
                                           float* __restrict__ F,
                                           int t, int p)
{
    float4 pt = *(const float4*)(xyzt + (size_t)(t * BP + p) * 4);

    #pragma unroll 1
    for (int l = 0; l < NLVL; l++) {
        float r = (float)c_res[l];
        float px = pt.x * r, py = pt.y * r, pz = pt.z * r, pw = pt.w * r;
        float fx = floorf(px), fy = floorf(py), fz = floorf(pz), ft = floorf(pw);
        float wx = px - fx, wy = py - fy, wz = pz - fz, wt = pw - ft;
        unsigned cx = (unsigned)fx, cy = (unsigned)fy,
                 cz = (unsigned)fz, ct = (unsigned)ft;

        unsigned hx0 = cx,               hx1 = cx + 1u;
        unsigned hy0 = cy * 2654435761u, hy1 = (cy + 1u) * 2654435761u;
        unsigned hz0 = cz * 805459861u,  hz1 = (cz + 1u) * 805459861u;
        unsigned ht0 = ct * 3674653429u, ht1 = (ct + 1u) * 3674653429u;

        float wx0 = 1.f - wx, wy0 = 1.f - wy, wz0 = 1.f - wz, wt0 = 1.f - wt;

        const float2* tl = (const float2*)table + (size_t)l * TSZ;
        float a0 = 0.f, a1 = 0.f;

        if ((cx & 1u) == 0u) {
            const float4* t4 = (const float4*)tl;
            #pragma unroll
            for (int c8 = 0; c8 < 8; c8++) {
                unsigned hyy = (c8 & 1) ? hy1 : hy0;
                unsigned hzz = (c8 & 2) ? hz1 : hz0;
                unsigned htt = (c8 & 4) ? ht1 : ht0;
                unsigned idx0 = (hx0 ^ hyy ^ hzz ^ htt) & TMASK;
                float wyzt = ((c8 & 1) ? wy : wy0) * ((c8 & 2) ? wz : wz0) *
                             ((c8 & 4) ? wt : wt0);
                float w0 = wx0 * wyzt, w1 = wx * wyzt;
                float4 v = __ldg(&t4[idx0 >> 1]);
                bool hi = (idx0 & 1u);
                float f0x = hi ? v.z : v.x, f0y = hi ? v.w : v.y;
                float f1x = hi ? v.x : v.z, f1y = hi ? v.y : v.w;
                a0 = fmaf(f0x, w0, a0); a0 = fmaf(f1x, w1, a0);
                a1 = fmaf(f0y, w0, a1); a1 = fmaf(f1y, w1, a1);
            }
        } else {
            #pragma unroll
            for (int c8 = 0; c8 < 16; c8++) {
                unsigned hxx = (c8 & 1) ? hx1 : hx0;
                unsigned hyy = (c8 & 2) ? hy1 : hy0;
                unsigned hzz = (c8 & 4) ? hz1 : hz0;
                unsigned htt = (c8 & 8) ? ht1 : ht0;
                unsigned idx = (hxx ^ hyy ^ hzz ^ htt) & TMASK;
                float w = ((c8 & 1) ? wx : wx0) * ((c8 & 2) ? wy : wy0) *
                          ((c8 & 4) ? wz : wz0) * ((c8 & 8) ? wt : wt0);
                float2 f = __ldg(&tl[idx]);
                a0 = fmaf(f.x, w, a0);
                a1 = fmaf(f.y, w, a1);
            }
        }
        F[(2 * l + 0) * S + p] = a0;
        F[(2 * l + 1) * S + p] = a1;
    }
}

// ---------------------------------------------------------------------------
// Consumer: full MLP for one tile (128 threads: warps 0-3).
// ---------------------------------------------------------------------------
__device__ __forceinline__ void mlp_tile(float* __restrict__ s,
                                         const float* __restrict__ F,
                                         const float* __restrict__ dirs,
                                         float* __restrict__ out,
                                         int t, int warp, int lane, int tid)
{
    const int gbase = t * BP;
    float* B0 = s + OFF_B0;
    float* B1 = s + OFF_B1;

    gemmW<32, true>(F, B0, OFF_SW0, warp, lane);
    BARC();
    gemmW<64, true>(B0, B1, OFF_SW1, warp, lane);
    BARC();
    gemm16W(B1, B0, warp, lane);               // h -> B0 rows 0..15
    BARC();

    // color input assembly into B1 rows 0..41; sigma out
    {
        const int p = tid;
        const int gn = gbase + p;
        float d0 = dirs[(size_t)gn * 3 + 0];
        float d1 = dirs[(size_t)gn * 3 + 1];
        float d2 = dirs[(size_t)gn * 3 + 2];
        B1[0 * S + p] = d0;
        B1[1 * S + p] = d1;
        B1[2 * S + p] = d2;
        float dd[3] = {d0, d1, d2};
        #pragma unroll
        for (int f = 0; f < 4; f++) {
            float fr = (float)(1 << f);
            #pragma unroll
            for (int c = 0; c < 3; c++) {
                float sv, cv;
                sincosf(dd[c] * fr, &sv, &cv);
                B1[(3 + f * 3 + c) * S + p]  = sv;
                B1[(15 + f * 3 + c) * S + p] = cv;
            }
        }
        #pragma unroll
        for (int k = 0; k < 15; k++)
            B1[(27 + k) * S + p] = B0[(1 + k) * S + p];
        out[gn] = B0[0 * S + p];
    }
    BARC();

    gemmW<42, true>(B1, B0, OFF_CW0, warp, lane);
    BARC();
    gemmW<64, true>(B0, B1, OFF_CW1, warp, lane);
    BARC();

    // final 64 -> 3 + sigmoid
    {
        const int p = tid;
        const int gn = gbase + p;
        float r0 = 0.f, r1 = 0.f, r2 = 0.f;
        #pragma unroll 8
        for (int i = 0; i < 64; i++) {
            float xv = B1[i * S + p];
            r0 = fmaf(xv, c_w[OFF_CW2 + i * 3 + 0], r0);
            r1 = fmaf(xv, c_w[OFF_CW2 + i * 3 + 1], r1);
            r2 = fmaf(xv, c_w[OFF_CW2 + i * 3 + 2], r2);
        }
        out[(size_t)NPTS + (size_t)gn * 3 + 0] = 1.f / (1.f + __expf(-r0));
        out[(size_t)NPTS + (size_t)gn * 3 + 1] = 1.f / (1.f + __expf(-r1));
        out[(size_t)NPTS + (size_t)gn * 3 + 2] = 1.f / (1.f + __expf(-r2));
    }
}

// ---------------------------------------------------------------------------
// Fused pipelined kernel: warps 0-3 consume (MLP), warps 4-7 produce (hash).
// ---------------------------------------------------------------------------
__global__ __launch_bounds__(256, 2) void fused_kernel(
    const float* __restrict__ xyzt,
    const float* __restrict__ dirs,
    const float* __restrict__ table,
    float* __restrict__ out)
{
    extern __shared__ float s[];
    const int tid = threadIdx.x;
    const int warp = tid >> 5, lane = tid & 31;
    const bool producer = (tid >= 128);
    const int p = tid & 127;

    // prologue: produce F0 for first tile
    int t = blockIdx.x;
    if (producer)
        hash_point(xyzt, table, s + OFF_F0, t, p);
    __syncthreads();

    int k = 0;
    for (; t < NTILES; t += GRID, k++) {
        if (producer) {
            int tn = t + GRID;
            if (tn < NTILES)
                hash_point(xyzt, table, s + ((k + 1) & 1 ? OFF_F1 : OFF_F0),
                           tn, p);
        } else {
            mlp_tile(s, s + ((k & 1) ? OFF_F1 : OFF_F0), dirs, out,
                     t, warp, lane, tid);
        }
        __syncthreads();
    }
}

// ---------------------------------------------------------------------------
extern "C" void kernel_launch(void* const* d_in, const int* in_sizes, int n_in,
                              void* d_out, int out_size)
{
    const float* xyzt  = (const float*)d_in[0];
    const float* dirs  = (const float*)d_in[1];
    const float* table = (const float*)d_in[2];

    cudaMemcpyToSymbolAsync(c_w, d_in[3], 2048 * 4, OFF_SW0 * 4,
                            cudaMemcpyDeviceToDevice);
    cudaMemcpyToSymbolAsync(c_w, d_in[4], 4096 * 4, OFF_SW1 * 4,
                            cudaMemcpyDeviceToDevice);
    cudaMemcpyToSymbolAsync(c_w, d_in[5], 1024 * 4, OFF_SW2 * 4,
                            cudaMemcpyDeviceToDevice);
    cudaMemcpyToSymbolAsync(c_w, d_in[6], 2688 * 4, OFF_CW0 * 4,
                            cudaMemcpyDeviceToDevice);
    cudaMemcpyToSymbolAsync(c_w, d_in[7], 4096 * 4, OFF_CW1 * 4,
                            cudaMemcpyDeviceToDevice);
    cudaMemcpyToSymbolAsync(c_w, d_in[8], 192 * 4, OFF_CW2 * 4,
                            cudaMemcpyDeviceToDevice);

    cudaFuncSetAttribute(fused_kernel, cudaFuncAttributeMaxDynamicSharedMemorySize,
                         SMEM_BYTES);

    fused_kernel<<<GRID, 256, SMEM_BYTES>>>(xyzt, dirs, table, (float*)d_out);
}